// round 1
// baseline (speedup 1.0000x reference)
#include <cuda_runtime.h>
#include <math.h>

#define BATCH 4096
#define B2    8192       // 2*BATCH rows per branch
#define D     64
#define TM    128
#define TN    128
#define TMP   132        // padded leading dim (multiple of 4 for float4 LDS)
#define NCTILE (B2 / TN) // 64
#define LSE_BLOCKS (2 * (B2 / TM))  // 128
#define PREP_BLOCKS 1024            // 8192 warps, one per (branch, i)

// log2(e) / TEMPERATURE
#define SCALE_LOG2 7.213475204444817f
#define LN2 0.6931471805599453f

__device__ float g_X[2][B2 * D];            // [branch][row][d], 4MB total
__device__ float g_lse_partial[LSE_BLOCKS];
__device__ float g_pos_partial[PREP_BLOCKS];

// Fast 2^x on the FMA pipe (avoids MUFU throughput wall: 134M exps needed).
// Valid for x <= 0 (we only ever exponentiate (t - rowmax) <= 0). ~2.4e-6 rel err.
__device__ __forceinline__ float exp2_fast(float x) {
    x = fmaxf(x, -126.0f);
    float r = x + 12582912.0f;           // round-to-nearest via FP magic
    float k = r - 12582912.0f;
    float f = x - k;                     // f in [-0.5, 0.5]
    float p = 1.3333558146e-3f;
    p = fmaf(p, f, 9.6181291076e-3f);
    p = fmaf(p, f, 5.5504108664e-2f);
    p = fmaf(p, f, 2.4022650696e-1f);
    p = fmaf(p, f, 6.9314718056e-1f);
    p = fmaf(p, f, 1.0f);
    int s = (__float_as_int(r) << 23) + 0x3F800000;  // 2^k exponent bits
    return p * __int_as_float(s);
}

// ---------------------------------------------------------------------------
// Prep: gather embeddings, L2-normalize the user branch, write X = [v1; v2],
// and accumulate the positive-pair dot sums (fixed-order, deterministic).
// One warp per (branch, i) pair.
// ---------------------------------------------------------------------------
__global__ void __launch_bounds__(256) prep_kernel(
    const int* __restrict__ u_list, const int* __restrict__ i_list,
    const float* __restrict__ u1t, const float* __restrict__ i1t,
    const float* __restrict__ u2t, const float* __restrict__ i2t)
{
    int w      = blockIdx.x * 8 + (threadIdx.x >> 5);
    int lane   = threadIdx.x & 31;
    int branch = w >> 12;          // 0 = user, 1 = item
    int i      = w & (BATCH - 1);

    int idx = (branch ? i_list : u_list)[i];
    const float* t1 = branch ? i1t : u1t;
    const float* t2 = branch ? i2t : u2t;

    float2 a = ((const float2*)(t1 + (size_t)idx * D))[lane];
    float2 b = ((const float2*)(t2 + (size_t)idx * D))[lane];

    if (branch == 0) {
        float na = a.x * a.x + a.y * a.y;
        float nb = b.x * b.x + b.y * b.y;
        #pragma unroll
        for (int o = 16; o; o >>= 1) {
            na += __shfl_xor_sync(0xffffffffu, na, o);
            nb += __shfl_xor_sync(0xffffffffu, nb, o);
        }
        float ia = rsqrtf(na), ib = rsqrtf(nb);
        a.x *= ia; a.y *= ia;
        b.x *= ib; b.y *= ib;
    }

    float* X = g_X[branch];
    ((float2*)(X + (size_t)i * D))[lane]           = a;
    ((float2*)(X + (size_t)(BATCH + i) * D))[lane] = b;

    float pd = a.x * b.x + a.y * b.y;   // positive-pair dot (pre-/T)
    #pragma unroll
    for (int o = 16; o; o >>= 1) pd += __shfl_xor_sync(0xffffffffu, pd, o);

    __shared__ float sp[8];
    if (lane == 0) sp[threadIdx.x >> 5] = pd;
    __syncthreads();
    if (threadIdx.x == 0) {
        float s = 0.f;
        #pragma unroll
        for (int k = 0; k < 8; k++) s += sp[k];
        g_pos_partial[blockIdx.x] = s;
    }
}

// ---------------------------------------------------------------------------
// Main: per-row logsumexp of S = X X^T / T with diagonal masked to -inf.
// Flash-style online (max, sum) in base-2. 128 CTAs x 256 thr, 8x8 microtiles.
// ---------------------------------------------------------------------------
__device__ __forceinline__ void load_tile_T(float* dst, const float* __restrict__ src,
                                            int row0, int tid)
{
    #pragma unroll
    for (int v = 0; v < 8; v++) {
        int lin = v * 256 + tid;       // 0..2047 float4 slots (128 rows x 16)
        int r   = lin >> 4;
        int c4  = lin & 15;
        float4 f = ((const float4*)(src + (size_t)(row0 + r) * D))[c4];
        dst[(c4 * 4 + 0) * TMP + r] = f.x;
        dst[(c4 * 4 + 1) * TMP + r] = f.y;
        dst[(c4 * 4 + 2) * TMP + r] = f.z;
        dst[(c4 * 4 + 3) * TMP + r] = f.w;
    }
}

__global__ void __launch_bounds__(256) lse_kernel()
{
    extern __shared__ float smem[];
    float* Qs = smem;                 // [D][TMP] k-major
    float* Ks = smem + D * TMP;

    int branch = blockIdx.x >> 6;
    int rt     = blockIdx.x & (NCTILE - 1);
    const float* X = g_X[branch];

    int tid = threadIdx.x;
    int tx  = tid & 15;
    int ty  = tid >> 4;
    int row0 = rt * TM;

    load_tile_T(Qs, X, row0, tid);

    float m[8], s[8];
    #pragma unroll
    for (int r = 0; r < 8; r++) { m[r] = -INFINITY; s[r] = 0.f; }

    for (int ct = 0; ct < NCTILE; ct++) {
        __syncthreads();              // prev compute done (and Q visible on ct==0)
        load_tile_T(Ks, X, ct * TN, tid);
        __syncthreads();

        float acc[8][8];
        #pragma unroll
        for (int r = 0; r < 8; r++)
            #pragma unroll
            for (int c = 0; c < 8; c++) acc[r][c] = 0.f;

        #pragma unroll 8
        for (int k = 0; k < D; k++) {
            float4 a0 = *(const float4*)&Qs[k * TMP + ty * 8];
            float4 a1 = *(const float4*)&Qs[k * TMP + ty * 8 + 4];
            float4 b0 = *(const float4*)&Ks[k * TMP + tx * 8];
            float4 b1 = *(const float4*)&Ks[k * TMP + tx * 8 + 4];
            float av[8] = {a0.x, a0.y, a0.z, a0.w, a1.x, a1.y, a1.z, a1.w};
            float bv[8] = {b0.x, b0.y, b0.z, b0.w, b1.x, b1.y, b1.z, b1.w};
            #pragma unroll
            for (int r = 0; r < 8; r++)
                #pragma unroll
                for (int c = 0; c < 8; c++)
                    acc[r][c] = fmaf(av[r], bv[c], acc[r][c]);
        }

        // scale to base-2 logits (folds 1/T and log2e)
        #pragma unroll
        for (int r = 0; r < 8; r++)
            #pragma unroll
            for (int c = 0; c < 8; c++) acc[r][c] *= SCALE_LOG2;

        // diagonal mask: only when row tile == col tile and tx == ty
        if (ct == rt && tx == ty) {
            #pragma unroll
            for (int r = 0; r < 8; r++) acc[r][r] = -INFINITY;
        }

        // online LSE update per row (replicated across the 16 tx lanes)
        #pragma unroll
        for (int r = 0; r < 8; r++) {
            float v = acc[r][0];
            #pragma unroll
            for (int c = 1; c < 8; c++) v = fmaxf(v, acc[r][c]);
            v = fmaxf(v, __shfl_xor_sync(0xffffffffu, v, 1));
            v = fmaxf(v, __shfl_xor_sync(0xffffffffu, v, 2));
            v = fmaxf(v, __shfl_xor_sync(0xffffffffu, v, 4));
            v = fmaxf(v, __shfl_xor_sync(0xffffffffu, v, 8));

            float mn  = fmaxf(m[r], v);
            float fac = exp2_fast(m[r] - mn);   // m==-inf -> ~0, times s=0 -> 0
            float rs = 0.f;
            #pragma unroll
            for (int c = 0; c < 8; c++) rs += exp2_fast(acc[r][c] - mn);
            rs += __shfl_xor_sync(0xffffffffu, rs, 1);
            rs += __shfl_xor_sync(0xffffffffu, rs, 2);
            rs += __shfl_xor_sync(0xffffffffu, rs, 4);
            rs += __shfl_xor_sync(0xffffffffu, rs, 8);

            s[r] = s[r] * fac + rs;
            m[r] = mn;
        }
    }

    // per-CTA sum of row LSEs (natural log units)
    float loc = 0.f;
    if (tx == 0) {
        #pragma unroll
        for (int r = 0; r < 8; r++) loc += m[r] + log2f(s[r]);
        loc *= LN2;
    }
    __shared__ float red[16];
    if (tx == 0) red[ty] = loc;
    __syncthreads();
    if (tid == 0) {
        float t = 0.f;
        #pragma unroll
        for (int k = 0; k < 16; k++) t += red[k];
        g_lse_partial[blockIdx.x] = t;
    }
}

// ---------------------------------------------------------------------------
// Finalize: loss = sum(LSE)/(2B)  -  sum(pos)/(B*T)
// ---------------------------------------------------------------------------
__global__ void __launch_bounds__(256) finalize_kernel(float* __restrict__ out)
{
    int tid = threadIdx.x;
    float v = 0.f;
    for (int i = tid; i < LSE_BLOCKS; i += 256)
        v += g_lse_partial[i] * (1.0f / (float)B2);
    for (int i = tid; i < PREP_BLOCKS; i += 256)
        v -= g_pos_partial[i] * (1.0f / ((float)BATCH * 0.2f));

    __shared__ float sm[256];
    sm[tid] = v;
    __syncthreads();
    for (int o = 128; o; o >>= 1) {
        if (tid < o) sm[tid] += sm[tid + o];
        __syncthreads();
    }
    if (tid == 0) out[0] = sm[0];
}

extern "C" void kernel_launch(void* const* d_in, const int* in_sizes, int n_in,
                              void* d_out, int out_size)
{
    const int*   u_list = (const int*)  d_in[0];
    const int*   i_list = (const int*)  d_in[1];
    const float* u1     = (const float*)d_in[2];
    const float* i1     = (const float*)d_in[3];
    const float* u2     = (const float*)d_in[4];
    const float* i2     = (const float*)d_in[5];
    float* out = (float*)d_out;

    const int smem_bytes = 2 * D * TMP * (int)sizeof(float);  // 67584
    cudaFuncSetAttribute(lse_kernel, cudaFuncAttributeMaxDynamicSharedMemorySize,
                         smem_bytes);

    prep_kernel<<<PREP_BLOCKS, 256>>>(u_list, i_list, u1, i1, u2, i2);
    lse_kernel<<<LSE_BLOCKS, 256, smem_bytes>>>();
    finalize_kernel<<<1, 256>>>(out);
}

// round 3
// speedup vs baseline: 3.0129x; 3.0129x over previous
#include <cuda_runtime.h>
#include <cuda_bf16.h>
#include <math.h>
#include <stdint.h>

#define BATCH 4096
#define B2    8192                  // rows per branch (v1;v2)
#define NT2   128                   // 64-wide column tiles
#define LSE_BLOCKS 128              // 2 branches x 64 row tiles of 128
#define PREP_BLOCKS 1024
#define LN2F 0.6931471805599453f
// sqrt(log2(e)/T): folded into operands so the MMA emits base-2 logits.
#define ROOT_S 2.68579135f

#define BROW 272                    // padded B smem row stride (bytes)
#define BUFB (64 * BROW)            // one B tile buffer: 17408 B

__device__ __align__(256) __nv_bfloat16 g_Y[2][B2 * 128]; // [hi(64)|lo(64)]/row
__device__ float g_lse_partial[LSE_BLOCKS];
__device__ float g_pos_partial[PREP_BLOCKS];

// ---------------------------------------------------------------------------
__device__ __forceinline__ uint32_t smem_u32(const void* p) {
    uint32_t a;
    asm("{ .reg .u64 t; cvta.to.shared.u64 t, %1; cvt.u32.u64 %0, t; }" : "=r"(a) : "l"(p));
    return a;
}
__device__ __forceinline__ float ex2(float x) {
    float y; asm("ex2.approx.f32 %0, %1;" : "=f"(y) : "f"(x)); return y;
}
__device__ __forceinline__ float lg2(float x) {
    float y; asm("lg2.approx.f32 %0, %1;" : "=f"(y) : "f"(x)); return y;
}
__device__ __forceinline__ void ldsm4(uint32_t* r, uint32_t addr) {
    asm volatile("ldmatrix.sync.aligned.m8n8.x4.shared.b16 {%0,%1,%2,%3}, [%4];"
        : "=r"(r[0]), "=r"(r[1]), "=r"(r[2]), "=r"(r[3]) : "r"(addr));
}
__device__ __forceinline__ void mma16816(float* c, const uint32_t* a,
                                         uint32_t b0, uint32_t b1) {
    asm volatile("mma.sync.aligned.m16n8k16.row.col.f32.bf16.bf16.f32 "
        "{%0,%1,%2,%3}, {%4,%5,%6,%7}, {%8,%9}, {%0,%1,%2,%3};"
        : "+f"(c[0]), "+f"(c[1]), "+f"(c[2]), "+f"(c[3])
        : "r"(a[0]), "r"(a[1]), "r"(a[2]), "r"(a[3]), "r"(b0), "r"(b1));
}

// ---------------------------------------------------------------------------
// Prep: gather, L2-normalize user branch, scale by ROOT_S, bf16 hi/lo split.
// ---------------------------------------------------------------------------
__global__ void __launch_bounds__(256) prep_kernel(
    const int* __restrict__ u_list, const int* __restrict__ i_list,
    const float* __restrict__ u1t, const float* __restrict__ i1t,
    const float* __restrict__ u2t, const float* __restrict__ i2t)
{
    int w      = blockIdx.x * 8 + (threadIdx.x >> 5);
    int lane   = threadIdx.x & 31;
    int branch = w >> 12;
    int i      = w & (BATCH - 1);

    int idx = (branch ? i_list : u_list)[i];
    const float* t1 = branch ? i1t : u1t;
    const float* t2 = branch ? i2t : u2t;

    float2 a = ((const float2*)(t1 + (size_t)idx * 64))[lane];
    float2 b = ((const float2*)(t2 + (size_t)idx * 64))[lane];

    if (branch == 0) {
        float na = a.x * a.x + a.y * a.y;
        float nb = b.x * b.x + b.y * b.y;
        #pragma unroll
        for (int o = 16; o; o >>= 1) {
            na += __shfl_xor_sync(0xffffffffu, na, o);
            nb += __shfl_xor_sync(0xffffffffu, nb, o);
        }
        float ia = rsqrtf(na), ib = rsqrtf(nb);
        a.x *= ia; a.y *= ia;
        b.x *= ib; b.y *= ib;
    }

    float pd = a.x * b.x + a.y * b.y;
    #pragma unroll
    for (int o = 16; o; o >>= 1) pd += __shfl_xor_sync(0xffffffffu, pd, o);

    __nv_bfloat16* Y = g_Y[branch];
    #pragma unroll
    for (int which = 0; which < 2; which++) {
        float2 v = which ? b : a;
        int row  = which ? (BATCH + i) : i;
        float yx = v.x * ROOT_S, yy = v.y * ROOT_S;
        __nv_bfloat16 hx = __float2bfloat16(yx);
        __nv_bfloat16 hy = __float2bfloat16(yy);
        __nv_bfloat16 lx = __float2bfloat16(yx - __bfloat162float(hx));
        __nv_bfloat16 ly = __float2bfloat16(yy - __bfloat162float(hy));
        __nv_bfloat162* rp = (__nv_bfloat162*)(Y + (size_t)row * 128);
        rp[lane]      = __nv_bfloat162(hx, hy);
        rp[32 + lane] = __nv_bfloat162(lx, ly);
    }

    __shared__ float sp_[8];
    if (lane == 0) sp_[threadIdx.x >> 5] = pd;
    __syncthreads();
    if (threadIdx.x == 0) {
        float s = 0.f;
        #pragma unroll
        for (int k = 0; k < 8; k++) s += sp_[k];
        g_pos_partial[blockIdx.x] = s;
    }
}

// ---------------------------------------------------------------------------
// Epilogue: 32 acc values -> 4 per-row running (m, s) logsumexp states.
// ---------------------------------------------------------------------------
template<bool DIAG>
__device__ __forceinline__ void epi(float acc[2][4][4], float* m, float* s,
                                    int grow0, int gcol0)
{
    #pragma unroll
    for (int mf = 0; mf < 2; mf++)
    #pragma unroll
    for (int h = 0; h < 2; h++) {
        float v[8];
        #pragma unroll
        for (int nf = 0; nf < 4; nf++) {
            v[nf * 2]     = acc[mf][nf][h * 2];
            v[nf * 2 + 1] = acc[mf][nf][h * 2 + 1];
        }
        if (DIAG) {
            int gr = grow0 + mf * 16 + h * 8;
            #pragma unroll
            for (int nf = 0; nf < 4; nf++) {
                if (gcol0 + nf * 8     == gr) v[nf * 2]     = -1e30f;
                if (gcol0 + nf * 8 + 1 == gr) v[nf * 2 + 1] = -1e30f;
            }
        }
        float mx = fmaxf(fmaxf(fmaxf(v[0], v[1]), fmaxf(v[2], v[3])),
                         fmaxf(fmaxf(v[4], v[5]), fmaxf(v[6], v[7])));
        int g = mf * 2 + h;
        if (mx > m[g]) { s[g] *= ex2(m[g] - mx); m[g] = mx; }
        float mm = m[g];
        float e0 = ex2(v[0] - mm), e1 = ex2(v[1] - mm);
        float e2 = ex2(v[2] - mm), e3 = ex2(v[3] - mm);
        float e4 = ex2(v[4] - mm), e5 = ex2(v[5] - mm);
        float e6 = ex2(v[6] - mm), e7 = ex2(v[7] - mm);
        s[g] += ((e0 + e1) + (e2 + e3)) + ((e4 + e5) + (e6 + e7));
    }
}

// ---------------------------------------------------------------------------
// Main: per (branch, 128-row tile) CTA. 8 warps as 4(m) x 2(n); warp tile
// 32m x 32n; column tile 64; K=192 via bf16 hi/lo x3 (hi*hi + lo*hi + hi*lo).
// ---------------------------------------------------------------------------
__global__ void __launch_bounds__(256, 1) lse_kernel()
{
    __shared__ __align__(16) unsigned char sB[2][BUFB];
    __shared__ float sMm[128][2], sMs[128][2];
    __shared__ float sRed[8];

    int tid  = threadIdx.x;
    int wid  = tid >> 5;
    int lane = tid & 31;
    int wy   = wid >> 1;            // m warp (0..3)
    int wx   = wid & 1;             // n warp (0..1)
    int gid  = lane >> 2;
    int tig  = lane & 3;

    int branch = blockIdx.x >> 6;
    int rt     = blockIdx.x & 63;
    const __nv_bfloat16* Y = g_Y[branch];
    const uint32_t* Y32 = (const uint32_t*)Y;

    // --- A fragments straight from gmem (L2-resident), kept in registers ---
    uint32_t ahi[4][2][4], alo[4][2][4];
    int arow = rt * 128 + wy * 32;
    #pragma unroll
    for (int kk = 0; kk < 4; kk++)
    #pragma unroll
    for (int mf = 0; mf < 2; mf++) {
        int r0 = (arow + mf * 16 + gid) * 64 + kk * 8 + tig;
        int r1 = r0 + 8 * 64;
        ahi[kk][mf][0] = Y32[r0];          ahi[kk][mf][1] = Y32[r1];
        ahi[kk][mf][2] = Y32[r0 + 4];      ahi[kk][mf][3] = Y32[r1 + 4];
        alo[kk][mf][0] = Y32[r0 + 32];     alo[kk][mf][1] = Y32[r1 + 32];
        alo[kk][mf][2] = Y32[r0 + 36];     alo[kk][mf][3] = Y32[r1 + 36];
    }

    // --- B ldmatrix per-lane addresses (x4 => 16n x 16k) ---
    uint32_t bbase_u = smem_u32(sB);
    int n_off = ((lane >> 4) & 1) * 8 + (lane & 7);
    int kb    = ((lane >> 3) & 1) * 16;
    uint32_t ba0 = bbase_u + (uint32_t)((wx * 32 + n_off) * BROW + kb);
    uint32_t ba1 = ba0 + 16 * BROW;

    // --- B tile copy mapping (gmem -> smem), 64B per thread ---
    int crow = tid >> 2, cq = tid & 3;

    // stage tile 0
    {
        const uint4* src = (const uint4*)(Y + (size_t)crow * 128) + cq * 4;
        uint4* dst = (uint4*)(sB[0] + crow * BROW + cq * 64);
        #pragma unroll
        for (int i2 = 0; i2 < 4; i2++) dst[i2] = src[i2];
    }
    __syncthreads();

    float m[4], s[4];
    #pragma unroll
    for (int g = 0; g < 4; g++) { m[g] = -1e30f; s[g] = 0.f; }
    float acc[2][4][4];
    #pragma unroll
    for (int mf = 0; mf < 2; mf++)
        #pragma unroll
        for (int nf = 0; nf < 4; nf++)
            #pragma unroll
            for (int j = 0; j < 4; j++) acc[mf][nf][j] = 0.f;

    int grow0 = rt * 128 + wy * 32 + gid;

    for (int ct = 0; ct < NT2; ct++) {
        // prefetch next tile into registers (hidden behind compute)
        uint4 p[4];
        if (ct + 1 < NT2) {
            const uint4* src =
                (const uint4*)(Y + (size_t)((ct + 1) * 64 + crow) * 128) + cq * 4;
            #pragma unroll
            for (int i2 = 0; i2 < 4; i2++) p[i2] = src[i2];
        }

        uint32_t bufo = (ct & 1) ? (uint32_t)BUFB : 0u;
        uint32_t a0 = ba0 + bufo, a1 = ba1 + bufo;

        #pragma unroll
        for (int kk = 0; kk < 4; kk++) {
            uint32_t bh0[4], bh1[4], bl0[4], bl1[4];
            ldsm4(bh0, a0 + kk * 32);
            ldsm4(bh1, a1 + kk * 32);
            ldsm4(bl0, a0 + 128 + kk * 32);
            ldsm4(bl1, a1 + 128 + kk * 32);
            #pragma unroll
            for (int mf = 0; mf < 2; mf++) {
                mma16816(acc[mf][0], ahi[kk][mf], bh0[0], bh0[1]);
                mma16816(acc[mf][1], ahi[kk][mf], bh0[2], bh0[3]);
                mma16816(acc[mf][2], ahi[kk][mf], bh1[0], bh1[1]);
                mma16816(acc[mf][3], ahi[kk][mf], bh1[2], bh1[3]);
                mma16816(acc[mf][0], alo[kk][mf], bh0[0], bh0[1]);
                mma16816(acc[mf][1], alo[kk][mf], bh0[2], bh0[3]);
                mma16816(acc[mf][2], alo[kk][mf], bh1[0], bh1[1]);
                mma16816(acc[mf][3], alo[kk][mf], bh1[2], bh1[3]);
                mma16816(acc[mf][0], ahi[kk][mf], bl0[0], bl0[1]);
                mma16816(acc[mf][1], ahi[kk][mf], bl0[2], bl0[3]);
                mma16816(acc[mf][2], ahi[kk][mf], bl1[0], bl1[1]);
                mma16816(acc[mf][3], ahi[kk][mf], bl1[2], bl1[3]);
            }
        }

        int gcol0 = ct * 64 + wx * 32 + 2 * tig;
        if ((ct >> 1) == rt) epi<true >(acc, m, s, grow0, gcol0);
        else                 epi<false>(acc, m, s, grow0, gcol0);

        #pragma unroll
        for (int mf = 0; mf < 2; mf++)
            #pragma unroll
            for (int nf = 0; nf < 4; nf++)
                #pragma unroll
                for (int j = 0; j < 4; j++) acc[mf][nf][j] = 0.f;

        if (ct + 1 < NT2) {
            uint4* dst = (uint4*)(sB[(ct + 1) & 1] + crow * BROW + cq * 64);
            #pragma unroll
            for (int i2 = 0; i2 < 4; i2++) dst[i2] = p[i2];
        }
        __syncthreads();
    }

    // --- merge: quad (tig) -> smem (wx) -> row LSE -> CTA sum ---
    #pragma unroll
    for (int g = 0; g < 4; g++) {
        #pragma unroll
        for (int off = 1; off <= 2; off <<= 1) {
            float om = __shfl_xor_sync(0xffffffffu, m[g], off);
            float os = __shfl_xor_sync(0xffffffffu, s[g], off);
            float mn = fmaxf(m[g], om);
            s[g] = s[g] * ex2(m[g] - mn) + os * ex2(om - mn);
            m[g] = mn;
        }
    }
    if (tig == 0) {
        #pragma unroll
        for (int g = 0; g < 4; g++) {
            int row_local = wy * 32 + (g >> 1) * 16 + (g & 1) * 8 + gid;
            sMm[row_local][wx] = m[g];
            sMs[row_local][wx] = s[g];
        }
    }
    __syncthreads();
    if (tid < 128) {
        float m0 = sMm[tid][0], m1 = sMm[tid][1];
        float mn = fmaxf(m0, m1);
        float st = sMs[tid][0] * ex2(m0 - mn) + sMs[tid][1] * ex2(m1 - mn);
        float lse = LN2F * (mn + lg2(st));
        #pragma unroll
        for (int o = 16; o; o >>= 1) lse += __shfl_xor_sync(0xffffffffu, lse, o);
        if (lane == 0) sRed[tid >> 5] = lse;
    }
    __syncthreads();
    if (tid == 0)
        g_lse_partial[blockIdx.x] = sRed[0] + sRed[1] + sRed[2] + sRed[3];
}

// ---------------------------------------------------------------------------
// Finalize: loss = sum(LSE)/(2B) - sum(pos)/(B*T)
// ---------------------------------------------------------------------------
__global__ void __launch_bounds__(256) finalize_kernel(float* __restrict__ out)
{
    int tid = threadIdx.x;
    float v = 0.f;
    for (int i = tid; i < LSE_BLOCKS; i += 256)
        v += g_lse_partial[i] * (1.0f / (float)B2);
    for (int i = tid; i < PREP_BLOCKS; i += 256)
        v -= g_pos_partial[i] * (1.0f / ((float)BATCH * 0.2f));

    __shared__ float sm[256];
    sm[tid] = v;
    __syncthreads();
    for (int o = 128; o; o >>= 1) {
        if (tid < o) sm[tid] += sm[tid + o];
        __syncthreads();
    }
    if (tid == 0) out[0] = sm[0];
}

extern "C" void kernel_launch(void* const* d_in, const int* in_sizes, int n_in,
                              void* d_out, int out_size)
{
    const int*   u_list = (const int*)  d_in[0];
    const int*   i_list = (const int*)  d_in[1];
    const float* u1     = (const float*)d_in[2];
    const float* i1     = (const float*)d_in[3];
    const float* u2     = (const float*)d_in[4];
    const float* i2     = (const float*)d_in[5];
    float* out = (float*)d_out;

    prep_kernel<<<PREP_BLOCKS, 256>>>(u_list, i_list, u1, i1, u2, i2);
    lse_kernel<<<LSE_BLOCKS, 256>>>();
    finalize_kernel<<<1, 256>>>(out);
}

// round 5
// speedup vs baseline: 3.6191x; 1.2012x over previous
#include <cuda_runtime.h>
#include <cuda_bf16.h>
#include <math.h>
#include <stdint.h>

#define BATCH 4096
#define B2    8192
#define LSE_BLOCKS 128              // 2 branches x 64 row tiles
#define PREP_BLOCKS 1024
#define LN2F 0.6931471805599453f
#define ROOT_S 2.68579135f          // sqrt(log2(e)/T) folded into operands

#define TROW 272                    // padded smem row stride (bytes)
#define TILE_SM (128 * TROW)        // 34816 B per staged tile
#define SMEM_RED 6144               // sRowM,sColM,sRowS,sColS
#define SMEM_REQ (2 * TILE_SM + SMEM_RED)

__device__ __align__(256) __nv_bfloat16 g_Y[2][B2 * 128]; // [hi(64)|lo(64)]/row
__device__ float g_s[2][64][64][128];   // per-(rowtile,coltile) partial sums
__device__ float g_mv[2][64][64][128];  // matching per-row max bases
__device__ float g_lse_partial[LSE_BLOCKS];
__device__ float g_pos_partial[PREP_BLOCKS];

// ---------------------------------------------------------------------------
__device__ __forceinline__ uint32_t smem_u32(const void* p) {
    uint32_t a;
    asm("{ .reg .u64 t; cvta.to.shared.u64 t, %1; cvt.u32.u64 %0, t; }" : "=r"(a) : "l"(p));
    return a;
}
__device__ __forceinline__ float ex2(float x) {
    float y; asm("ex2.approx.f32 %0, %1;" : "=f"(y) : "f"(x)); return y;
}
__device__ __forceinline__ float lg2(float x) {
    float y; asm("lg2.approx.f32 %0, %1;" : "=f"(y) : "f"(x)); return y;
}
__device__ __forceinline__ void ldsm4(uint32_t* r, uint32_t addr) {
    asm volatile("ldmatrix.sync.aligned.m8n8.x4.shared.b16 {%0,%1,%2,%3}, [%4];"
        : "=r"(r[0]), "=r"(r[1]), "=r"(r[2]), "=r"(r[3]) : "r"(addr));
}
__device__ __forceinline__ void mma16816(float* c, const uint32_t* a,
                                         uint32_t b0, uint32_t b1) {
    asm volatile("mma.sync.aligned.m16n8k16.row.col.f32.bf16.bf16.f32 "
        "{%0,%1,%2,%3}, {%4,%5,%6,%7}, {%8,%9}, {%0,%1,%2,%3};"
        : "+f"(c[0]), "+f"(c[1]), "+f"(c[2]), "+f"(c[3])
        : "r"(a[0]), "r"(a[1]), "r"(a[2]), "r"(a[3]), "r"(b0), "r"(b1));
}

// ---------------------------------------------------------------------------
// Prep: gather, L2-normalize user branch, scale by ROOT_S, bf16 hi/lo split.
// ---------------------------------------------------------------------------
__global__ void __launch_bounds__(256) prep_kernel(
    const int* __restrict__ u_list, const int* __restrict__ i_list,
    const float* __restrict__ u1t, const float* __restrict__ i1t,
    const float* __restrict__ u2t, const float* __restrict__ i2t)
{
    int w      = blockIdx.x * 8 + (threadIdx.x >> 5);
    int lane   = threadIdx.x & 31;
    int branch = w >> 12;
    int i      = w & (BATCH - 1);

    int idx = (branch ? i_list : u_list)[i];
    const float* t1 = branch ? i1t : u1t;
    const float* t2 = branch ? i2t : u2t;

    float2 a = ((const float2*)(t1 + (size_t)idx * 64))[lane];
    float2 b = ((const float2*)(t2 + (size_t)idx * 64))[lane];

    if (branch == 0) {
        float na = a.x * a.x + a.y * a.y;
        float nb = b.x * b.x + b.y * b.y;
        #pragma unroll
        for (int o = 16; o; o >>= 1) {
            na += __shfl_xor_sync(0xffffffffu, na, o);
            nb += __shfl_xor_sync(0xffffffffu, nb, o);
        }
        float ia = rsqrtf(na), ib = rsqrtf(nb);
        a.x *= ia; a.y *= ia;
        b.x *= ib; b.y *= ib;
    }

    float pd = a.x * b.x + a.y * b.y;
    #pragma unroll
    for (int o = 16; o; o >>= 1) pd += __shfl_xor_sync(0xffffffffu, pd, o);

    __nv_bfloat16* Y = g_Y[branch];
    #pragma unroll
    for (int which = 0; which < 2; which++) {
        float2 v = which ? b : a;
        int row  = which ? (BATCH + i) : i;
        float yx = v.x * ROOT_S, yy = v.y * ROOT_S;
        __nv_bfloat16 hx = __float2bfloat16(yx);
        __nv_bfloat16 hy = __float2bfloat16(yy);
        __nv_bfloat16 lx = __float2bfloat16(yx - __bfloat162float(hx));
        __nv_bfloat16 ly = __float2bfloat16(yy - __bfloat162float(hy));
        __nv_bfloat162* rp = (__nv_bfloat162*)(Y + (size_t)row * 128);
        rp[lane]      = __nv_bfloat162(hx, hy);
        rp[32 + lane] = __nv_bfloat162(lx, ly);
    }

    __shared__ float sp_[8];
    if (lane == 0) sp_[threadIdx.x >> 5] = pd;
    __syncthreads();
    if (threadIdx.x == 0) {
        float s = 0.f;
        #pragma unroll
        for (int k = 0; k < 8; k++) s += sp_[k];
        g_pos_partial[blockIdx.x] = s;
    }
}

// ---------------------------------------------------------------------------
// Tile kernel: one 128x128 tile (r,c), r <= c, per CTA. K=192 (bf16 hi/lo x3).
// Exports row sums (per-row max basis) to g_s/g_mv[b][r][c] and col sums
// (per-col max basis) to g_s/g_mv[b][c][r]. 8 warps (4m x 2n).
// ---------------------------------------------------------------------------
__global__ void __launch_bounds__(256, 2) tile_kernel()
{
    extern __shared__ unsigned char dsm[];
    unsigned char* sA = dsm;
    unsigned char* sB = dsm + TILE_SM;
    float* sRowM = (float*)(dsm + 2 * TILE_SM);          // [128][2]
    float* sColM = (float*)(dsm + 2 * TILE_SM + 1024);   // [128][4]
    float* sRowS = (float*)(dsm + 2 * TILE_SM + 3072);   // [128][2]
    float* sColS = (float*)(dsm + 2 * TILE_SM + 4096);   // [128][4]

    int tid  = threadIdx.x;
    int wid  = tid >> 5;
    int lane = tid & 31;
    int wy   = wid >> 1;            // m warp 0..3
    int wx   = wid & 1;             // n warp 0..1
    int gid  = lane >> 2;
    int tig  = lane & 3;

    // triangular decode: t -> (r,c), r <= c
    int t = blockIdx.x;
    int b = blockIdx.y;
    int r = (int)((129.0f - sqrtf(16641.0f - 8.0f * (float)t)) * 0.5f);
    while ((r + 1) * (129 - (r + 1)) / 2 <= t) r++;
    while (r * (129 - r) / 2 > t) r--;
    int c = r + (t - r * (129 - r) / 2);
    bool isdiag = (r == c);

    const __nv_bfloat16* Y = g_Y[b];

    // stage A (rows of tile r) and B (rows of tile c)
    {
        int row = tid >> 1, half = tid & 1;
        const uint4* srcA = (const uint4*)(Y + (size_t)(r * 128 + row) * 128) + half * 8;
        const uint4* srcB = (const uint4*)(Y + (size_t)(c * 128 + row) * 128) + half * 8;
        uint4* dA = (uint4*)(sA + row * TROW + half * 128);
        uint4* dB = (uint4*)(sB + row * TROW + half * 128);
        #pragma unroll
        for (int i = 0; i < 8; i++) dA[i] = srcA[i];
        #pragma unroll
        for (int i = 0; i < 8; i++) dB[i] = srcB[i];
    }
    __syncthreads();

    uint32_t sAu = smem_u32(sA), sBu = smem_u32(sB);
    uint32_t aAddr = sAu + (uint32_t)((wy * 32 + (lane & 7) + ((lane >> 3) & 1) * 8) * TROW
                                      + ((lane >> 4) & 1) * 16);
    uint32_t bAddr = sBu + (uint32_t)((wx * 64 + ((lane >> 4) & 1) * 8 + (lane & 7)) * TROW
                                      + ((lane >> 3) & 1) * 16);

    float acc[2][8][4];
    #pragma unroll
    for (int mf = 0; mf < 2; mf++)
        #pragma unroll
        for (int nf = 0; nf < 8; nf++)
            #pragma unroll
            for (int j = 0; j < 4; j++) acc[mf][nf][j] = 0.f;

    #pragma unroll
    for (int kk = 0; kk < 4; kk++) {
        uint32_t ah[2][4], al[2][4];
        ldsm4(ah[0], aAddr + kk * 32);
        ldsm4(ah[1], aAddr + 16 * TROW + kk * 32);
        ldsm4(al[0], aAddr + 128 + kk * 32);
        ldsm4(al[1], aAddr + 16 * TROW + 128 + kk * 32);
        #pragma unroll
        for (int ng = 0; ng < 4; ng++) {
            uint32_t bh[4], bl[4];
            ldsm4(bh, bAddr + ng * 16 * TROW + kk * 32);
            ldsm4(bl, bAddr + ng * 16 * TROW + 128 + kk * 32);
            #pragma unroll
            for (int mf = 0; mf < 2; mf++) {
                mma16816(acc[mf][ng * 2],     ah[mf], bh[0], bh[1]);
                mma16816(acc[mf][ng * 2 + 1], ah[mf], bh[2], bh[3]);
                mma16816(acc[mf][ng * 2],     al[mf], bh[0], bh[1]);
                mma16816(acc[mf][ng * 2 + 1], al[mf], bh[2], bh[3]);
                mma16816(acc[mf][ng * 2],     ah[mf], bl[0], bl[1]);
                mma16816(acc[mf][ng * 2 + 1], ah[mf], bl[2], bl[3]);
            }
        }
    }

    // diagonal mask (only on diag tiles)
    if (isdiag) {
        #pragma unroll
        for (int mf = 0; mf < 2; mf++)
            #pragma unroll
            for (int nf = 0; nf < 8; nf++)
                #pragma unroll
                for (int j = 0; j < 4; j++) {
                    int rl = wy * 32 + mf * 16 + (j >> 1) * 8 + gid;
                    int cl = wx * 64 + nf * 8 + tig * 2 + (j & 1);
                    if (rl == cl) acc[mf][nf][j] = -1e30f;
                }
    }

    // ---- per-row max (over this warp's 64 cols, then merge wx in smem) ----
    #pragma unroll
    for (int mf = 0; mf < 2; mf++)
        #pragma unroll
        for (int h = 0; h < 2; h++) {
            float v = -1e30f;
            #pragma unroll
            for (int nf = 0; nf < 8; nf++)
                v = fmaxf(v, fmaxf(acc[mf][nf][h * 2], acc[mf][nf][h * 2 + 1]));
            v = fmaxf(v, __shfl_xor_sync(0xffffffffu, v, 1));
            v = fmaxf(v, __shfl_xor_sync(0xffffffffu, v, 2));
            if (tig == 0)
                sRowM[(wy * 32 + mf * 16 + h * 8 + gid) * 2 + wx] = v;
        }
    // ---- per-col max (over this warp's 32 rows, then merge wy in smem) ----
    #pragma unroll
    for (int nf = 0; nf < 8; nf++)
        #pragma unroll
        for (int q = 0; q < 2; q++) {
            float v = -1e30f;
            #pragma unroll
            for (int mf = 0; mf < 2; mf++)
                #pragma unroll
                for (int h = 0; h < 2; h++) v = fmaxf(v, acc[mf][nf][h * 2 + q]);
            v = fmaxf(v, __shfl_xor_sync(0xffffffffu, v, 4));
            v = fmaxf(v, __shfl_xor_sync(0xffffffffu, v, 8));
            v = fmaxf(v, __shfl_xor_sync(0xffffffffu, v, 16));
            if (gid == 0)
                sColM[(wx * 64 + nf * 8 + tig * 2 + q) * 4 + wy] = v;
        }
    __syncthreads();

    // final per-row / per-col maxes this thread needs
    float rm[2][2], cm[8][2];
    #pragma unroll
    for (int mf = 0; mf < 2; mf++)
        #pragma unroll
        for (int h = 0; h < 2; h++) {
            int row = wy * 32 + mf * 16 + h * 8 + gid;
            rm[mf][h] = fmaxf(sRowM[row * 2], sRowM[row * 2 + 1]);
        }
    #pragma unroll
    for (int nf = 0; nf < 8; nf++)
        #pragma unroll
        for (int q = 0; q < 2; q++) {
            int col = wx * 64 + nf * 8 + tig * 2 + q;
            cm[nf][q] = fmaxf(fmaxf(sColM[col * 4], sColM[col * 4 + 1]),
                              fmaxf(sColM[col * 4 + 2], sColM[col * 4 + 3]));
        }

    // ---- row sums: exp2(acc - rowmax) ----
    #pragma unroll
    for (int mf = 0; mf < 2; mf++)
        #pragma unroll
        for (int h = 0; h < 2; h++) {
            float v = 0.f;
            float mmx = rm[mf][h];
            #pragma unroll
            for (int nf = 0; nf < 8; nf++)
                v += ex2(acc[mf][nf][h * 2] - mmx) + ex2(acc[mf][nf][h * 2 + 1] - mmx);
            v += __shfl_xor_sync(0xffffffffu, v, 1);
            v += __shfl_xor_sync(0xffffffffu, v, 2);
            if (tig == 0)
                sRowS[(wy * 32 + mf * 16 + h * 8 + gid) * 2 + wx] = v;
        }
    // ---- col sums: exp2(acc - colmax) (skip on diag tiles) ----
    if (!isdiag) {
        #pragma unroll
        for (int nf = 0; nf < 8; nf++)
            #pragma unroll
            for (int q = 0; q < 2; q++) {
                float v = 0.f;
                float mmx = cm[nf][q];
                #pragma unroll
                for (int mf = 0; mf < 2; mf++)
                    #pragma unroll
                    for (int h = 0; h < 2; h++) v += ex2(acc[mf][nf][h * 2 + q] - mmx);
                v += __shfl_xor_sync(0xffffffffu, v, 4);
                v += __shfl_xor_sync(0xffffffffu, v, 8);
                v += __shfl_xor_sync(0xffffffffu, v, 16);
                if (gid == 0)
                    sColS[(wx * 64 + nf * 8 + tig * 2 + q) * 4 + wy] = v;
            }
    }
    __syncthreads();

    if (tid < 128) {
        g_s[b][r][c][tid]  = sRowS[tid * 2] + sRowS[tid * 2 + 1];
        g_mv[b][r][c][tid] = fmaxf(sRowM[tid * 2], sRowM[tid * 2 + 1]);
        if (!isdiag) {
            g_s[b][c][r][tid]  = sColS[tid * 4] + sColS[tid * 4 + 1]
                               + sColS[tid * 4 + 2] + sColS[tid * 4 + 3];
            g_mv[b][c][r][tid] = fmaxf(fmaxf(sColM[tid * 4], sColM[tid * 4 + 1]),
                                       fmaxf(sColM[tid * 4 + 2], sColM[tid * 4 + 3]));
        }
    }
}

// ---------------------------------------------------------------------------
// Combine: per (branch, row tile, row) online-merge 64 (m, s) partials.
// ---------------------------------------------------------------------------
__global__ void __launch_bounds__(128) combine_kernel()
{
    int b   = blockIdx.x >> 6;
    int rt  = blockIdx.x & 63;
    int tid = threadIdx.x;
    __shared__ float sOut[4];

    float m = -1e30f, s = 0.f;
    #pragma unroll 8
    for (int ct = 0; ct < 64; ct++) {
        float mc = g_mv[b][rt][ct][tid];
        float sc = g_s[b][rt][ct][tid];
        float mn = fmaxf(m, mc);
        s = s * ex2(m - mn) + sc * ex2(mc - mn);
        m = mn;
    }
    float lse = LN2F * (m + lg2(s));
    #pragma unroll
    for (int o = 16; o; o >>= 1) lse += __shfl_xor_sync(0xffffffffu, lse, o);
    if ((tid & 31) == 0) sOut[tid >> 5] = lse;
    __syncthreads();
    if (tid == 0)
        g_lse_partial[blockIdx.x] = sOut[0] + sOut[1] + sOut[2] + sOut[3];
}

// ---------------------------------------------------------------------------
// Finalize: loss = sum(LSE)/(2B) - sum(pos)/(B*T)
// ---------------------------------------------------------------------------
__global__ void __launch_bounds__(256) finalize_kernel(float* __restrict__ out)
{
    int tid = threadIdx.x;
    float v = 0.f;
    for (int i = tid; i < LSE_BLOCKS; i += 256)
        v += g_lse_partial[i] * (1.0f / (float)B2);
    for (int i = tid; i < PREP_BLOCKS; i += 256)
        v -= g_pos_partial[i] * (1.0f / ((float)BATCH * 0.2f));

    __shared__ float sm[256];
    sm[tid] = v;
    __syncthreads();
    for (int o = 128; o; o >>= 1) {
        if (tid < o) sm[tid] += sm[tid + o];
        __syncthreads();
    }
    if (tid == 0) out[0] = sm[0];
}

extern "C" void kernel_launch(void* const* d_in, const int* in_sizes, int n_in,
                              void* d_out, int out_size)
{
    const int*   u_list = (const int*)  d_in[0];
    const int*   i_list = (const int*)  d_in[1];
    const float* u1     = (const float*)d_in[2];
    const float* i1     = (const float*)d_in[3];
    const float* u2     = (const float*)d_in[4];
    const float* i2     = (const float*)d_in[5];
    float* out = (float*)d_out;

    cudaFuncSetAttribute(tile_kernel, cudaFuncAttributeMaxDynamicSharedMemorySize,
                         SMEM_REQ);

    prep_kernel<<<PREP_BLOCKS, 256>>>(u_list, i_list, u1, i1, u2, i2);
    tile_kernel<<<dim3(2080, 2), 256, SMEM_REQ>>>();
    combine_kernel<<<LSE_BLOCKS, 128>>>();
    finalize_kernel<<<1, 256>>>(out);
}

// round 6
// speedup vs baseline: 3.8479x; 1.0632x over previous
#include <cuda_runtime.h>
#include <cuda_bf16.h>
#include <math.h>
#include <stdint.h>

#define BATCH 4096
#define B2    8192
#define LSE_BLOCKS 128              // 2 branches x 64 row tiles
#define PREP_BLOCKS 1024
#define LN2F 0.6931471805599453f
#define ROOT_S 2.68579135f          // sqrt(log2(e)/T) folded into operands

#define TROW 272                    // padded smem row stride (bytes)
#define TILE_SM (128 * TROW)        // 34816 B per staged tile
#define SMEM_RED 6144
#define SMEM_REQ (2 * TILE_SM + SMEM_RED)

__device__ __align__(256) __nv_bfloat16 g_Y[2][B2 * 128]; // [hi(64)|lo(64)]/row
__device__ float g_s[2][64][64][128];   // per-(rowtile,coltile) partial sums
__device__ float g_mv[2][64][64][128];  // matching per-row max bases
__device__ float g_lse_partial[LSE_BLOCKS];
__device__ float g_pos_partial[PREP_BLOCKS];
__device__ int   g_count = 0;           // combine last-block counter (self-reset)

// ---------------------------------------------------------------------------
__device__ __forceinline__ uint32_t smem_u32(const void* p) {
    uint32_t a;
    asm("{ .reg .u64 t; cvta.to.shared.u64 t, %1; cvt.u32.u64 %0, t; }" : "=r"(a) : "l"(p));
    return a;
}
__device__ __forceinline__ float ex2(float x) {
    float y; asm("ex2.approx.f32 %0, %1;" : "=f"(y) : "f"(x)); return y;
}
__device__ __forceinline__ float lg2(float x) {
    float y; asm("lg2.approx.f32 %0, %1;" : "=f"(y) : "f"(x)); return y;
}
__device__ __forceinline__ void ldsm4(uint32_t* r, uint32_t addr) {
    asm volatile("ldmatrix.sync.aligned.m8n8.x4.shared.b16 {%0,%1,%2,%3}, [%4];"
        : "=r"(r[0]), "=r"(r[1]), "=r"(r[2]), "=r"(r[3]) : "r"(addr));
}
__device__ __forceinline__ void mma16816(float* c, const uint32_t* a,
                                         uint32_t b0, uint32_t b1) {
    asm volatile("mma.sync.aligned.m16n8k16.row.col.f32.bf16.bf16.f32 "
        "{%0,%1,%2,%3}, {%4,%5,%6,%7}, {%8,%9}, {%0,%1,%2,%3};"
        : "+f"(c[0]), "+f"(c[1]), "+f"(c[2]), "+f"(c[3])
        : "r"(a[0]), "r"(a[1]), "r"(a[2]), "r"(a[3]), "r"(b0), "r"(b1));
}

// ---------------------------------------------------------------------------
// Prep: gather, L2-normalize user branch, scale by ROOT_S, bf16 hi/lo split.
// ---------------------------------------------------------------------------
__global__ void __launch_bounds__(256) prep_kernel(
    const int* __restrict__ u_list, const int* __restrict__ i_list,
    const float* __restrict__ u1t, const float* __restrict__ i1t,
    const float* __restrict__ u2t, const float* __restrict__ i2t)
{
    int w      = blockIdx.x * 8 + (threadIdx.x >> 5);
    int lane   = threadIdx.x & 31;
    int branch = w >> 12;
    int i      = w & (BATCH - 1);

    int idx = (branch ? i_list : u_list)[i];
    const float* t1 = branch ? i1t : u1t;
    const float* t2 = branch ? i2t : u2t;

    float2 a = ((const float2*)(t1 + (size_t)idx * 64))[lane];
    float2 b = ((const float2*)(t2 + (size_t)idx * 64))[lane];

    if (branch == 0) {
        float na = a.x * a.x + a.y * a.y;
        float nb = b.x * b.x + b.y * b.y;
        #pragma unroll
        for (int o = 16; o; o >>= 1) {
            na += __shfl_xor_sync(0xffffffffu, na, o);
            nb += __shfl_xor_sync(0xffffffffu, nb, o);
        }
        float ia = rsqrtf(na), ib = rsqrtf(nb);
        a.x *= ia; a.y *= ia;
        b.x *= ib; b.y *= ib;
    }

    float pd = a.x * b.x + a.y * b.y;
    #pragma unroll
    for (int o = 16; o; o >>= 1) pd += __shfl_xor_sync(0xffffffffu, pd, o);

    __nv_bfloat16* Y = g_Y[branch];
    #pragma unroll
    for (int which = 0; which < 2; which++) {
        float2 v = which ? b : a;
        int row  = which ? (BATCH + i) : i;
        float yx = v.x * ROOT_S, yy = v.y * ROOT_S;
        __nv_bfloat16 hx = __float2bfloat16(yx);
        __nv_bfloat16 hy = __float2bfloat16(yy);
        __nv_bfloat16 lx = __float2bfloat16(yx - __bfloat162float(hx));
        __nv_bfloat16 ly = __float2bfloat16(yy - __bfloat162float(hy));
        __nv_bfloat162* rp = (__nv_bfloat162*)(Y + (size_t)row * 128);
        rp[lane]      = __nv_bfloat162(hx, hy);
        rp[32 + lane] = __nv_bfloat162(lx, ly);
    }

    __shared__ float sp_[8];
    if (lane == 0) sp_[threadIdx.x >> 5] = pd;
    __syncthreads();
    if (threadIdx.x == 0) {
        float s = 0.f;
        #pragma unroll
        for (int k = 0; k < 8; k++) s += sp_[k];
        g_pos_partial[blockIdx.x] = s;
    }
}

// ---------------------------------------------------------------------------
// GEMM mainloop. FULL=true: hi*hi + lo*hi + hi*lo (K=192 equivalent).
// FULL=false: hi*hi only (user branch, normalized inputs -> tiny logits).
// ---------------------------------------------------------------------------
template<bool FULL>
__device__ __forceinline__ void mainloop(float acc[2][8][4],
                                         uint32_t aAddr, uint32_t bAddr)
{
    #pragma unroll
    for (int kk = 0; kk < 4; kk++) {
        uint32_t ah[2][4], al[2][4];
        ldsm4(ah[0], aAddr + kk * 32);
        ldsm4(ah[1], aAddr + 16 * TROW + kk * 32);
        if (FULL) {
            ldsm4(al[0], aAddr + 128 + kk * 32);
            ldsm4(al[1], aAddr + 16 * TROW + 128 + kk * 32);
        }
        #pragma unroll
        for (int ng = 0; ng < 4; ng++) {
            uint32_t bh[4], bl[4];
            ldsm4(bh, bAddr + ng * 16 * TROW + kk * 32);
            if (FULL) ldsm4(bl, bAddr + ng * 16 * TROW + 128 + kk * 32);
            #pragma unroll
            for (int mf = 0; mf < 2; mf++) {
                mma16816(acc[mf][ng * 2],     ah[mf], bh[0], bh[1]);
                mma16816(acc[mf][ng * 2 + 1], ah[mf], bh[2], bh[3]);
                if (FULL) {
                    mma16816(acc[mf][ng * 2],     al[mf], bh[0], bh[1]);
                    mma16816(acc[mf][ng * 2 + 1], al[mf], bh[2], bh[3]);
                    mma16816(acc[mf][ng * 2],     ah[mf], bl[0], bl[1]);
                    mma16816(acc[mf][ng * 2 + 1], ah[mf], bl[2], bl[3]);
                }
            }
        }
    }
}

// ---------------------------------------------------------------------------
// Tile kernel: one 128x128 tile (r,c), r <= c, per CTA. Exports row sums
// (per-row max basis) to g_s/g_mv[b][r][c], col sums to g_s/g_mv[b][c][r].
// ---------------------------------------------------------------------------
__global__ void __launch_bounds__(256, 2) tile_kernel()
{
    extern __shared__ unsigned char dsm[];
    unsigned char* sA = dsm;
    unsigned char* sB = dsm + TILE_SM;
    float* sRowM = (float*)(dsm + 2 * TILE_SM);          // [128][2]
    float* sColM = (float*)(dsm + 2 * TILE_SM + 1024);   // [128][4]
    float* sRowS = (float*)(dsm + 2 * TILE_SM + 3072);   // [128][2]
    float* sColS = (float*)(dsm + 2 * TILE_SM + 4096);   // [128][4]

    int tid  = threadIdx.x;
    int wid  = tid >> 5;
    int lane = tid & 31;
    int wy   = wid >> 1;
    int wx   = wid & 1;
    int gid  = lane >> 2;
    int tig  = lane & 3;

    // triangular decode: t -> (r,c), r <= c
    int t = blockIdx.x;
    int b = blockIdx.y;
    int r = (int)((129.0f - sqrtf(16641.0f - 8.0f * (float)t)) * 0.5f);
    while ((r + 1) * (129 - (r + 1)) / 2 <= t) r++;
    while (r * (129 - r) / 2 > t) r--;
    int c = r + (t - r * (129 - r) / 2);
    bool isdiag = (r == c);

    const __nv_bfloat16* Y = g_Y[b];

    // stage A (rows of tile r) and B (rows of tile c)
    {
        int row = tid >> 1, half = tid & 1;
        const uint4* srcA = (const uint4*)(Y + (size_t)(r * 128 + row) * 128) + half * 8;
        const uint4* srcB = (const uint4*)(Y + (size_t)(c * 128 + row) * 128) + half * 8;
        uint4* dA = (uint4*)(sA + row * TROW + half * 128);
        uint4* dB = (uint4*)(sB + row * TROW + half * 128);
        #pragma unroll
        for (int i = 0; i < 8; i++) dA[i] = srcA[i];
        #pragma unroll
        for (int i = 0; i < 8; i++) dB[i] = srcB[i];
    }
    __syncthreads();

    uint32_t sAu = smem_u32(sA), sBu = smem_u32(sB);
    uint32_t aAddr = sAu + (uint32_t)((wy * 32 + (lane & 7) + ((lane >> 3) & 1) * 8) * TROW
                                      + ((lane >> 4) & 1) * 16);
    uint32_t bAddr = sBu + (uint32_t)((wx * 64 + ((lane >> 4) & 1) * 8 + (lane & 7)) * TROW
                                      + ((lane >> 3) & 1) * 16);

    float acc[2][8][4];
    #pragma unroll
    for (int mf = 0; mf < 2; mf++)
        #pragma unroll
        for (int nf = 0; nf < 8; nf++)
            #pragma unroll
            for (int j = 0; j < 4; j++) acc[mf][nf][j] = 0.f;

    if (b == 0) mainloop<false>(acc, aAddr, bAddr);   // user: hi*hi only
    else        mainloop<true >(acc, aAddr, bAddr);   // item: full 3-term

    // diagonal mask (only on diag tiles)
    if (isdiag) {
        #pragma unroll
        for (int mf = 0; mf < 2; mf++)
            #pragma unroll
            for (int nf = 0; nf < 8; nf++)
                #pragma unroll
                for (int j = 0; j < 4; j++) {
                    int rl = wy * 32 + mf * 16 + (j >> 1) * 8 + gid;
                    int cl = wx * 64 + nf * 8 + tig * 2 + (j & 1);
                    if (rl == cl) acc[mf][nf][j] = -1e30f;
                }
    }

    // ---- per-row max ----
    #pragma unroll
    for (int mf = 0; mf < 2; mf++)
        #pragma unroll
        for (int h = 0; h < 2; h++) {
            float v = -1e30f;
            #pragma unroll
            for (int nf = 0; nf < 8; nf++)
                v = fmaxf(v, fmaxf(acc[mf][nf][h * 2], acc[mf][nf][h * 2 + 1]));
            v = fmaxf(v, __shfl_xor_sync(0xffffffffu, v, 1));
            v = fmaxf(v, __shfl_xor_sync(0xffffffffu, v, 2));
            if (tig == 0)
                sRowM[(wy * 32 + mf * 16 + h * 8 + gid) * 2 + wx] = v;
        }
    // ---- per-col max ----
    #pragma unroll
    for (int nf = 0; nf < 8; nf++)
        #pragma unroll
        for (int q = 0; q < 2; q++) {
            float v = -1e30f;
            #pragma unroll
            for (int mf = 0; mf < 2; mf++)
                #pragma unroll
                for (int h = 0; h < 2; h++) v = fmaxf(v, acc[mf][nf][h * 2 + q]);
            v = fmaxf(v, __shfl_xor_sync(0xffffffffu, v, 4));
            v = fmaxf(v, __shfl_xor_sync(0xffffffffu, v, 8));
            v = fmaxf(v, __shfl_xor_sync(0xffffffffu, v, 16));
            if (gid == 0)
                sColM[(wx * 64 + nf * 8 + tig * 2 + q) * 4 + wy] = v;
        }
    __syncthreads();

    float rm[2][2], cm[8][2];
    #pragma unroll
    for (int mf = 0; mf < 2; mf++)
        #pragma unroll
        for (int h = 0; h < 2; h++) {
            int row = wy * 32 + mf * 16 + h * 8 + gid;
            rm[mf][h] = fmaxf(sRowM[row * 2], sRowM[row * 2 + 1]);
        }
    #pragma unroll
    for (int nf = 0; nf < 8; nf++)
        #pragma unroll
        for (int q = 0; q < 2; q++) {
            int col = wx * 64 + nf * 8 + tig * 2 + q;
            cm[nf][q] = fmaxf(fmaxf(sColM[col * 4], sColM[col * 4 + 1]),
                              fmaxf(sColM[col * 4 + 2], sColM[col * 4 + 3]));
        }

    // ---- row sums: exp2(acc - rowmax) ----
    #pragma unroll
    for (int mf = 0; mf < 2; mf++)
        #pragma unroll
        for (int h = 0; h < 2; h++) {
            float v = 0.f;
            float mmx = rm[mf][h];
            #pragma unroll
            for (int nf = 0; nf < 8; nf++)
                v += ex2(acc[mf][nf][h * 2] - mmx) + ex2(acc[mf][nf][h * 2 + 1] - mmx);
            v += __shfl_xor_sync(0xffffffffu, v, 1);
            v += __shfl_xor_sync(0xffffffffu, v, 2);
            if (tig == 0)
                sRowS[(wy * 32 + mf * 16 + h * 8 + gid) * 2 + wx] = v;
        }
    // ---- col sums: exp2(acc - colmax) (skip on diag tiles) ----
    if (!isdiag) {
        #pragma unroll
        for (int nf = 0; nf < 8; nf++)
            #pragma unroll
            for (int q = 0; q < 2; q++) {
                float v = 0.f;
                float mmx = cm[nf][q];
                #pragma unroll
                for (int mf = 0; mf < 2; mf++)
                    #pragma unroll
                    for (int h = 0; h < 2; h++) v += ex2(acc[mf][nf][h * 2 + q] - mmx);
                v += __shfl_xor_sync(0xffffffffu, v, 4);
                v += __shfl_xor_sync(0xffffffffu, v, 8);
                v += __shfl_xor_sync(0xffffffffu, v, 16);
                if (gid == 0)
                    sColS[(wx * 64 + nf * 8 + tig * 2 + q) * 4 + wy] = v;
            }
    }
    __syncthreads();

    if (tid < 128) {
        g_s[b][r][c][tid]  = sRowS[tid * 2] + sRowS[tid * 2 + 1];
        g_mv[b][r][c][tid] = fmaxf(sRowM[tid * 2], sRowM[tid * 2 + 1]);
        if (!isdiag) {
            g_s[b][c][r][tid]  = sColS[tid * 4] + sColS[tid * 4 + 1]
                               + sColS[tid * 4 + 2] + sColS[tid * 4 + 3];
            g_mv[b][c][r][tid] = fmaxf(fmaxf(sColM[tid * 4], sColM[tid * 4 + 1]),
                                       fmaxf(sColM[tid * 4 + 2], sColM[tid * 4 + 3]));
        }
    }
}

// ---------------------------------------------------------------------------
// Combine + fused finalize: per (branch, row tile, row) online-merge 64
// (m, s) partials; the last block to finish computes the final loss.
// ---------------------------------------------------------------------------
__global__ void __launch_bounds__(128) combine_kernel(float* __restrict__ out)
{
    int b   = blockIdx.x >> 6;
    int rt  = blockIdx.x & 63;
    int tid = threadIdx.x;
    __shared__ float sOut[4];
    __shared__ int sLast;

    float m = -1e30f, s = 0.f;
    #pragma unroll 8
    for (int ct = 0; ct < 64; ct++) {
        float mc = g_mv[b][rt][ct][tid];
        float sc = g_s[b][rt][ct][tid];
        float mn = fmaxf(m, mc);
        s = s * ex2(m - mn) + sc * ex2(mc - mn);
        m = mn;
    }
    float lse = LN2F * (m + lg2(s));
    #pragma unroll
    for (int o = 16; o; o >>= 1) lse += __shfl_xor_sync(0xffffffffu, lse, o);
    if ((tid & 31) == 0) sOut[tid >> 5] = lse;
    __syncthreads();
    if (tid == 0) {
        g_lse_partial[blockIdx.x] = sOut[0] + sOut[1] + sOut[2] + sOut[3];
        __threadfence();
        int old = atomicAdd(&g_count, 1);
        sLast = (old == LSE_BLOCKS - 1) ? 1 : 0;
    }
    __syncthreads();

    if (sLast) {
        __threadfence();
        float v = g_lse_partial[tid] * (1.0f / (float)B2);
        for (int i = tid; i < PREP_BLOCKS; i += 128)
            v -= g_pos_partial[i] * (1.0f / ((float)BATCH * 0.2f));
        #pragma unroll
        for (int o = 16; o; o >>= 1) v += __shfl_xor_sync(0xffffffffu, v, o);
        __shared__ float sF[4];
        if ((tid & 31) == 0) sF[tid >> 5] = v;
        __syncthreads();
        if (tid == 0) {
            out[0] = sF[0] + sF[1] + sF[2] + sF[3];
            g_count = 0;   // reset for next graph replay
        }
    }
}

extern "C" void kernel_launch(void* const* d_in, const int* in_sizes, int n_in,
                              void* d_out, int out_size)
{
    const int*   u_list = (const int*)  d_in[0];
    const int*   i_list = (const int*)  d_in[1];
    const float* u1     = (const float*)d_in[2];
    const float* i1     = (const float*)d_in[3];
    const float* u2     = (const float*)d_in[4];
    const float* i2     = (const float*)d_in[5];
    float* out = (float*)d_out;

    cudaFuncSetAttribute(tile_kernel, cudaFuncAttributeMaxDynamicSharedMemorySize,
                         SMEM_REQ);

    prep_kernel<<<PREP_BLOCKS, 256>>>(u_list, i_list, u1, i1, u2, i2);
    tile_kernel<<<dim3(2080, 2), 256, SMEM_REQ>>>();
    combine_kernel<<<LSE_BLOCKS, 128>>>(out);
}

// round 7
// speedup vs baseline: 5.2811x; 1.3725x over previous
#include <cuda_runtime.h>
#include <cuda_bf16.h>
#include <math.h>
#include <stdint.h>

#define BATCH 4096
#define B2    8192
#define NTILE 2080                  // triangular 128x128 tiles per branch
#define LSE_BLOCKS 128
#define PREP_BLOCKS 1024
#define GRID_P 296                  // persistent CTAs (2 per SM)
#define WU 2                        // user tile weight
#define WI 3                        // item tile weight
#define WTOT (NTILE * (WU + WI))    // 10400
#define LN2F 0.6931471805599453f
#define ROOT_S 2.68579135f          // sqrt(log2(e)/T) folded into operands
#define UBASE 8.0f                  // fixed user-branch basis (logits in +-7.22)

#define TROW 272                    // padded smem row stride (bytes)
#define TILE_SM (128 * TROW)        // 34816 B
#define SMEM_RED 6144
#define SMEM_REQ (3 * TILE_SM + SMEM_RED)   // A + B0 + B1 + reductions

__device__ __align__(256) __nv_bfloat16 g_Y[2][B2 * 128]; // [hi(64)|lo(64)]/row
__device__ float g_s[2][64][64][128];
__device__ float g_mv[2][64][64][128];
__device__ float g_lse_partial[LSE_BLOCKS];
__device__ float g_pos_partial[PREP_BLOCKS];
__device__ int   g_count = 0;

// ---------------------------------------------------------------------------
__device__ __forceinline__ uint32_t smem_u32(const void* p) {
    uint32_t a;
    asm("{ .reg .u64 t; cvta.to.shared.u64 t, %1; cvt.u32.u64 %0, t; }" : "=r"(a) : "l"(p));
    return a;
}
__device__ __forceinline__ float ex2(float x) {
    float y; asm("ex2.approx.f32 %0, %1;" : "=f"(y) : "f"(x)); return y;
}
__device__ __forceinline__ float lg2(float x) {
    float y; asm("lg2.approx.f32 %0, %1;" : "=f"(y) : "f"(x)); return y;
}
__device__ __forceinline__ void ldsm4(uint32_t* r, uint32_t addr) {
    asm volatile("ldmatrix.sync.aligned.m8n8.x4.shared.b16 {%0,%1,%2,%3}, [%4];"
        : "=r"(r[0]), "=r"(r[1]), "=r"(r[2]), "=r"(r[3]) : "r"(addr));
}
__device__ __forceinline__ void mma16816(float* c, const uint32_t* a,
                                         uint32_t b0, uint32_t b1) {
    asm volatile("mma.sync.aligned.m16n8k16.row.col.f32.bf16.bf16.f32 "
        "{%0,%1,%2,%3}, {%4,%5,%6,%7}, {%8,%9}, {%0,%1,%2,%3};"
        : "+f"(c[0]), "+f"(c[1]), "+f"(c[2]), "+f"(c[3])
        : "r"(a[0]), "r"(a[1]), "r"(a[2]), "r"(a[3]), "r"(b0), "r"(b1));
}
#define CP16(dst, src) \
    asm volatile("cp.async.cg.shared.global [%0], [%1], 16;" :: "r"(dst), "l"(src))
#define CP_COMMIT() asm volatile("cp.async.commit_group;" ::: "memory")
#define CP_WAIT0()  asm volatile("cp.async.wait_group 0;" ::: "memory")

// ---------------------------------------------------------------------------
// Prep: gather, L2-normalize user branch, scale by ROOT_S, bf16 hi/lo split.
// ---------------------------------------------------------------------------
__global__ void __launch_bounds__(256) prep_kernel(
    const int* __restrict__ u_list, const int* __restrict__ i_list,
    const float* __restrict__ u1t, const float* __restrict__ i1t,
    const float* __restrict__ u2t, const float* __restrict__ i2t)
{
    int w      = blockIdx.x * 8 + (threadIdx.x >> 5);
    int lane   = threadIdx.x & 31;
    int branch = w >> 12;
    int i      = w & (BATCH - 1);

    int idx = (branch ? i_list : u_list)[i];
    const float* t1 = branch ? i1t : u1t;
    const float* t2 = branch ? i2t : u2t;

    float2 a = ((const float2*)(t1 + (size_t)idx * 64))[lane];
    float2 b = ((const float2*)(t2 + (size_t)idx * 64))[lane];

    if (branch == 0) {
        float na = a.x * a.x + a.y * a.y;
        float nb = b.x * b.x + b.y * b.y;
        #pragma unroll
        for (int o = 16; o; o >>= 1) {
            na += __shfl_xor_sync(0xffffffffu, na, o);
            nb += __shfl_xor_sync(0xffffffffu, nb, o);
        }
        float ia = rsqrtf(na), ib = rsqrtf(nb);
        a.x *= ia; a.y *= ia;
        b.x *= ib; b.y *= ib;
    }

    float pd = a.x * b.x + a.y * b.y;
    #pragma unroll
    for (int o = 16; o; o >>= 1) pd += __shfl_xor_sync(0xffffffffu, pd, o);

    __nv_bfloat16* Y = g_Y[branch];
    #pragma unroll
    for (int which = 0; which < 2; which++) {
        float2 v = which ? b : a;
        int row  = which ? (BATCH + i) : i;
        float yx = v.x * ROOT_S, yy = v.y * ROOT_S;
        __nv_bfloat16 hx = __float2bfloat16(yx);
        __nv_bfloat16 hy = __float2bfloat16(yy);
        __nv_bfloat16 lx = __float2bfloat16(yx - __bfloat162float(hx));
        __nv_bfloat16 ly = __float2bfloat16(yy - __bfloat162float(hy));
        __nv_bfloat162* rp = (__nv_bfloat162*)(Y + (size_t)row * 128);
        rp[lane]      = __nv_bfloat162(hx, hy);
        rp[32 + lane] = __nv_bfloat162(lx, ly);
    }

    __shared__ float sp_[8];
    if (lane == 0) sp_[threadIdx.x >> 5] = pd;
    __syncthreads();
    if (threadIdx.x == 0) {
        float s = 0.f;
        #pragma unroll
        for (int k = 0; k < 8; k++) s += sp_[k];
        g_pos_partial[blockIdx.x] = s;
    }
}

// ---------------------------------------------------------------------------
// cp.async stage: 128 rows x (NC16*16) bytes into padded smem tile.
// NC16=16: full 256B rows (item); NC16=8: hi half only (user).
// ---------------------------------------------------------------------------
template<int NC16>
__device__ __forceinline__ void stage_tile(uint32_t sdst,
                                           const __nv_bfloat16* __restrict__ Y,
                                           int row0, int tid)
{
    #pragma unroll
    for (int i = 0; i < (128 * NC16) / 256; i++) {
        int l   = i * 256 + tid;
        int row = l / NC16;
        int col = l - row * NC16;
        uint32_t dst = sdst + (uint32_t)(row * TROW + col * 16);
        const char* src = (const char*)(Y + (size_t)(row0 + row) * 128) + col * 16;
        CP16(dst, src);
    }
}

// ---------------------------------------------------------------------------
// GEMM mainloop. FULL: hi*hi + lo*hi + hi*lo. else hi*hi only.
// ---------------------------------------------------------------------------
template<bool FULL>
__device__ __forceinline__ void mainloop(float acc[2][8][4],
                                         uint32_t aAddr, uint32_t bAddr)
{
    #pragma unroll
    for (int kk = 0; kk < 4; kk++) {
        uint32_t ah[2][4], al[2][4];
        ldsm4(ah[0], aAddr + kk * 32);
        ldsm4(ah[1], aAddr + 16 * TROW + kk * 32);
        if (FULL) {
            ldsm4(al[0], aAddr + 128 + kk * 32);
            ldsm4(al[1], aAddr + 16 * TROW + 128 + kk * 32);
        }
        #pragma unroll
        for (int ng = 0; ng < 4; ng++) {
            uint32_t bh[4], bl[4];
            ldsm4(bh, bAddr + ng * 16 * TROW + kk * 32);
            if (FULL) ldsm4(bl, bAddr + ng * 16 * TROW + 128 + kk * 32);
            #pragma unroll
            for (int mf = 0; mf < 2; mf++) {
                mma16816(acc[mf][ng * 2],     ah[mf], bh[0], bh[1]);
                mma16816(acc[mf][ng * 2 + 1], ah[mf], bh[2], bh[3]);
                if (FULL) {
                    mma16816(acc[mf][ng * 2],     al[mf], bh[0], bh[1]);
                    mma16816(acc[mf][ng * 2 + 1], al[mf], bh[2], bh[3]);
                    mma16816(acc[mf][ng * 2],     ah[mf], bl[0], bl[1]);
                    mma16816(acc[mf][ng * 2 + 1], ah[mf], bl[2], bl[3]);
                }
            }
        }
    }
}

// triangular decode: t -> (r, c), r <= c
__device__ __forceinline__ void decode_tile(int t, int& r, int& c)
{
    r = (int)((129.0f - sqrtf(16641.0f - 8.0f * (float)t)) * 0.5f);
    while ((r + 1) * (129 - (r + 1)) / 2 <= t) r++;
    while (r * (129 - r) / 2 > t) r--;
    c = r + (t - r * (129 - r) / 2);
}

// ---------------------------------------------------------------------------
// Persistent tile kernel: weighted chunks of (user, item) tiles; A-resident
// per row; B double-buffered via cp.async issued ahead of the mainloop.
// ---------------------------------------------------------------------------
__global__ void __launch_bounds__(256, 2) tile_kernel()
{
    extern __shared__ unsigned char dsm[];
    unsigned char* sA = dsm;
    float* sRowM = (float*)(dsm + 3 * TILE_SM);
    float* sColM = (float*)(dsm + 3 * TILE_SM + 1024);
    float* sRowS = (float*)(dsm + 3 * TILE_SM + 3072);
    float* sColS = (float*)(dsm + 3 * TILE_SM + 4096);

    int tid  = threadIdx.x;
    int lane = tid & 31;
    int wid  = tid >> 5;
    int wy   = wid >> 1;
    int wx   = wid & 1;
    int gid  = lane >> 2;
    int tig  = lane & 3;

    // weighted chunk [wlo, whi)
    int k   = blockIdx.x;
    int wlo = (int)(((long long)k * WTOT) / GRID_P);
    int whi = (int)(((long long)(k + 1) * WTOT) / GRID_P);
    int u0 = (wlo + 1) >> 1, u1 = (whi + 1) >> 1;
    if (u1 > NTILE) u1 = NTILE;
    if (u0 > u1) u0 = u1;
    int lo = wlo - NTILE * WU; if (lo < 0) lo = 0;
    int hi = whi - NTILE * WU; if (hi < 0) hi = 0;
    int i0 = (lo + 2) / 3, i1 = (hi + 2) / 3;
    if (i1 > NTILE) i1 = NTILE;
    if (i0 > i1) i0 = i1;
    int nu = u1 - u0, ni = i1 - i0;
    int n = nu + ni;
    if (n == 0) return;

    uint32_t sAu = smem_u32(sA);
    uint32_t sB0 = sAu + TILE_SM;

    uint32_t aAddr0 = sAu + (uint32_t)((wy * 32 + (lane & 7) + ((lane >> 3) & 1) * 8) * TROW
                                       + ((lane >> 4) & 1) * 16);
    uint32_t bOff   = (uint32_t)((wx * 64 + ((lane >> 4) & 1) * 8 + (lane & 7)) * TROW
                                 + ((lane >> 3) & 1) * 16);

    // tile j -> (b, t)
    auto get_bt = [&](int j, int& b, int& t) {
        if (j < nu) { b = 0; t = u0 + j; }
        else        { b = 1; t = i0 + (j - nu); }
    };

    int b, t, r, c;
    get_bt(0, b, t);
    decode_tile(t, r, c);

    // prologue: stage A(row r) and B(col c) into buf0
    if (b == 0) { stage_tile<8>(sAu, g_Y[0], r * 128, tid);
                  stage_tile<8>(sB0, g_Y[0], c * 128, tid); }
    else        { stage_tile<16>(sAu, g_Y[1], r * 128, tid);
                  stage_tile<16>(sB0, g_Y[1], c * 128, tid); }
    CP_COMMIT();

    int buf = 0;
    for (int j = 0; j < n; j++) {
        int bn = 0, tn = 0, rn = 0, cn = 0;
        bool have_next = (j + 1 < n);
        if (have_next) { get_bt(j + 1, bn, tn); decode_tile(tn, rn, cn); }

        CP_WAIT0();
        __syncthreads();

        // issue next B into the other buffer (overlaps mainloop + epilogue)
        if (have_next) {
            uint32_t sBn = sAu + TILE_SM + (uint32_t)((buf ^ 1) * TILE_SM);
            if (bn == 0) stage_tile<8>(sBn, g_Y[0], cn * 128, tid);
            else         stage_tile<16>(sBn, g_Y[1], cn * 128, tid);
            CP_COMMIT();
        }

        uint32_t bAddr = sAu + TILE_SM + (uint32_t)(buf * TILE_SM) + bOff;

        float acc[2][8][4];
        #pragma unroll
        for (int mf = 0; mf < 2; mf++)
            #pragma unroll
            for (int nf = 0; nf < 8; nf++)
                #pragma unroll
                for (int jj = 0; jj < 4; jj++) acc[mf][nf][jj] = 0.f;

        if (b == 0) mainloop<false>(acc, aAddr0, bAddr);
        else        mainloop<true >(acc, aAddr0, bAddr);

        __syncthreads();   // A reads complete

        // restage A if next tile uses a different (b, r)
        if (have_next && (bn != b || rn != r)) {
            if (bn == 0) stage_tile<8>(sAu, g_Y[0], rn * 128, tid);
            else         stage_tile<16>(sAu, g_Y[1], rn * 128, tid);
            CP_COMMIT();
        }

        bool isdiag = (r == c);
        if (isdiag) {
            #pragma unroll
            for (int mf = 0; mf < 2; mf++)
                #pragma unroll
                for (int nf = 0; nf < 8; nf++)
                    #pragma unroll
                    for (int jj = 0; jj < 4; jj++) {
                        int rl = wy * 32 + mf * 16 + ((jj >> 1) & 1) * 8 + gid;
                        int cl = wx * 64 + nf * 8 + tig * 2 + (jj & 1);
                        if (rl == cl) acc[mf][nf][jj] = -1e30f;
                    }
        }

        if (b == 0) {
            // -------- user branch: fixed basis UBASE, single exp pass --------
            #pragma unroll
            for (int mf = 0; mf < 2; mf++)
                #pragma unroll
                for (int nf = 0; nf < 8; nf++)
                    #pragma unroll
                    for (int jj = 0; jj < 4; jj++)
                        acc[mf][nf][jj] = ex2(acc[mf][nf][jj] - UBASE);

            #pragma unroll
            for (int mf = 0; mf < 2; mf++)
                #pragma unroll
                for (int h = 0; h < 2; h++) {
                    float v = 0.f;
                    #pragma unroll
                    for (int nf = 0; nf < 8; nf++)
                        v += acc[mf][nf][h * 2] + acc[mf][nf][h * 2 + 1];
                    v += __shfl_xor_sync(0xffffffffu, v, 1);
                    v += __shfl_xor_sync(0xffffffffu, v, 2);
                    if (tig == 0)
                        sRowS[(wy * 32 + mf * 16 + h * 8 + gid) * 2 + wx] = v;
                }
            if (!isdiag) {
                #pragma unroll
                for (int nf = 0; nf < 8; nf++)
                    #pragma unroll
                    for (int q = 0; q < 2; q++) {
                        float v = 0.f;
                        #pragma unroll
                        for (int mf = 0; mf < 2; mf++)
                            #pragma unroll
                            for (int h = 0; h < 2; h++) v += acc[mf][nf][h * 2 + q];
                        v += __shfl_xor_sync(0xffffffffu, v, 4);
                        v += __shfl_xor_sync(0xffffffffu, v, 8);
                        v += __shfl_xor_sync(0xffffffffu, v, 16);
                        if (gid == 0)
                            sColS[(wx * 64 + nf * 8 + tig * 2 + q) * 4 + wy] = v;
                    }
            }
            __syncthreads();
            if (tid < 128) {
                g_s[0][r][c][tid]  = sRowS[tid * 2] + sRowS[tid * 2 + 1];
                g_mv[0][r][c][tid] = UBASE;
                if (!isdiag) {
                    g_s[0][c][r][tid]  = sColS[tid * 4] + sColS[tid * 4 + 1]
                                       + sColS[tid * 4 + 2] + sColS[tid * 4 + 3];
                    g_mv[0][c][r][tid] = UBASE;
                }
            }
            __syncthreads();
        } else {
            // -------- item branch: exact per-row / per-col bases --------
            #pragma unroll
            for (int mf = 0; mf < 2; mf++)
                #pragma unroll
                for (int h = 0; h < 2; h++) {
                    float v = -1e30f;
                    #pragma unroll
                    for (int nf = 0; nf < 8; nf++)
                        v = fmaxf(v, fmaxf(acc[mf][nf][h * 2], acc[mf][nf][h * 2 + 1]));
                    v = fmaxf(v, __shfl_xor_sync(0xffffffffu, v, 1));
                    v = fmaxf(v, __shfl_xor_sync(0xffffffffu, v, 2));
                    if (tig == 0)
                        sRowM[(wy * 32 + mf * 16 + h * 8 + gid) * 2 + wx] = v;
                }
            #pragma unroll
            for (int nf = 0; nf < 8; nf++)
                #pragma unroll
                for (int q = 0; q < 2; q++) {
                    float v = -1e30f;
                    #pragma unroll
                    for (int mf = 0; mf < 2; mf++)
                        #pragma unroll
                        for (int h = 0; h < 2; h++) v = fmaxf(v, acc[mf][nf][h * 2 + q]);
                    v = fmaxf(v, __shfl_xor_sync(0xffffffffu, v, 4));
                    v = fmaxf(v, __shfl_xor_sync(0xffffffffu, v, 8));
                    v = fmaxf(v, __shfl_xor_sync(0xffffffffu, v, 16));
                    if (gid == 0)
                        sColM[(wx * 64 + nf * 8 + tig * 2 + q) * 4 + wy] = v;
                }
            __syncthreads();

            float rm[2][2], cm[8][2];
            #pragma unroll
            for (int mf = 0; mf < 2; mf++)
                #pragma unroll
                for (int h = 0; h < 2; h++) {
                    int row = wy * 32 + mf * 16 + h * 8 + gid;
                    rm[mf][h] = fmaxf(sRowM[row * 2], sRowM[row * 2 + 1]);
                }
            #pragma unroll
            for (int nf = 0; nf < 8; nf++)
                #pragma unroll
                for (int q = 0; q < 2; q++) {
                    int col = wx * 64 + nf * 8 + tig * 2 + q;
                    cm[nf][q] = fmaxf(fmaxf(sColM[col * 4], sColM[col * 4 + 1]),
                                      fmaxf(sColM[col * 4 + 2], sColM[col * 4 + 3]));
                }

            #pragma unroll
            for (int mf = 0; mf < 2; mf++)
                #pragma unroll
                for (int h = 0; h < 2; h++) {
                    float v = 0.f, mmx = rm[mf][h];
                    #pragma unroll
                    for (int nf = 0; nf < 8; nf++)
                        v += ex2(acc[mf][nf][h * 2] - mmx)
                           + ex2(acc[mf][nf][h * 2 + 1] - mmx);
                    v += __shfl_xor_sync(0xffffffffu, v, 1);
                    v += __shfl_xor_sync(0xffffffffu, v, 2);
                    if (tig == 0)
                        sRowS[(wy * 32 + mf * 16 + h * 8 + gid) * 2 + wx] = v;
                }
            if (!isdiag) {
                #pragma unroll
                for (int nf = 0; nf < 8; nf++)
                    #pragma unroll
                    for (int q = 0; q < 2; q++) {
                        float v = 0.f, mmx = cm[nf][q];
                        #pragma unroll
                        for (int mf = 0; mf < 2; mf++)
                            #pragma unroll
                            for (int h = 0; h < 2; h++)
                                v += ex2(acc[mf][nf][h * 2 + q] - mmx);
                        v += __shfl_xor_sync(0xffffffffu, v, 4);
                        v += __shfl_xor_sync(0xffffffffu, v, 8);
                        v += __shfl_xor_sync(0xffffffffu, v, 16);
                        if (gid == 0)
                            sColS[(wx * 64 + nf * 8 + tig * 2 + q) * 4 + wy] = v;
                    }
            }
            __syncthreads();
            if (tid < 128) {
                g_s[1][r][c][tid]  = sRowS[tid * 2] + sRowS[tid * 2 + 1];
                g_mv[1][r][c][tid] = fmaxf(sRowM[tid * 2], sRowM[tid * 2 + 1]);
                if (!isdiag) {
                    g_s[1][c][r][tid]  = sColS[tid * 4] + sColS[tid * 4 + 1]
                                       + sColS[tid * 4 + 2] + sColS[tid * 4 + 3];
                    g_mv[1][c][r][tid] = fmaxf(fmaxf(sColM[tid * 4], sColM[tid * 4 + 1]),
                                               fmaxf(sColM[tid * 4 + 2], sColM[tid * 4 + 3]));
                }
            }
            __syncthreads();
        }

        b = bn; t = tn; r = rn; c = cn;
        buf ^= 1;
    }
}

// ---------------------------------------------------------------------------
// Combine + fused finalize.
// ---------------------------------------------------------------------------
__global__ void __launch_bounds__(128) combine_kernel(float* __restrict__ out)
{
    int b   = blockIdx.x >> 6;
    int rt  = blockIdx.x & 63;
    int tid = threadIdx.x;
    __shared__ float sOut[4];
    __shared__ int sLast;

    float m = -1e30f, s = 0.f;
    #pragma unroll 8
    for (int ct = 0; ct < 64; ct++) {
        float mc = g_mv[b][rt][ct][tid];
        float sc = g_s[b][rt][ct][tid];
        float mn = fmaxf(m, mc);
        s = s * ex2(m - mn) + sc * ex2(mc - mn);
        m = mn;
    }
    float lse = LN2F * (m + lg2(s));
    #pragma unroll
    for (int o = 16; o; o >>= 1) lse += __shfl_xor_sync(0xffffffffu, lse, o);
    if ((tid & 31) == 0) sOut[tid >> 5] = lse;
    __syncthreads();
    if (tid == 0) {
        g_lse_partial[blockIdx.x] = sOut[0] + sOut[1] + sOut[2] + sOut[3];
        __threadfence();
        int old = atomicAdd(&g_count, 1);
        sLast = (old == LSE_BLOCKS - 1) ? 1 : 0;
    }
    __syncthreads();

    if (sLast) {
        __threadfence();
        float v = g_lse_partial[tid] * (1.0f / (float)B2);
        for (int i = tid; i < PREP_BLOCKS; i += 128)
            v -= g_pos_partial[i] * (1.0f / ((float)BATCH * 0.2f));
        #pragma unroll
        for (int o = 16; o; o >>= 1) v += __shfl_xor_sync(0xffffffffu, v, o);
        __shared__ float sF[4];
        if ((tid & 31) == 0) sF[tid >> 5] = v;
        __syncthreads();
        if (tid == 0) {
            out[0] = sF[0] + sF[1] + sF[2] + sF[3];
            g_count = 0;
        }
    }
}

extern "C" void kernel_launch(void* const* d_in, const int* in_sizes, int n_in,
                              void* d_out, int out_size)
{
    const int*   u_list = (const int*)  d_in[0];
    const int*   i_list = (const int*)  d_in[1];
    const float* u1     = (const float*)d_in[2];
    const float* i1     = (const float*)d_in[3];
    const float* u2     = (const float*)d_in[4];
    const float* i2     = (const float*)d_in[5];
    float* out = (float*)d_out;

    cudaFuncSetAttribute(tile_kernel, cudaFuncAttributeMaxDynamicSharedMemorySize,
                         SMEM_REQ);

    prep_kernel<<<PREP_BLOCKS, 256>>>(u_list, i_list, u1, i1, u2, i2);
    tile_kernel<<<GRID_P, 256, SMEM_REQ>>>();
    combine_kernel<<<LSE_BLOCKS, 128>>>(out);
}